// round 6
// baseline (speedup 1.0000x reference)
#include <cuda_runtime.h>

#define Hh 128
#define Ww 128
#define NB 32
#define CCH 16
#define NITER 30

#define TW 16
#define TH 8
#define IW 18
#define IH 10
#define IWP 19
#define NPAIR 64   // pairs per tile

typedef unsigned long long ULL;

// persistent state — double buffered (intra-launch halo race avoidance)
__device__ float g_bufA[NB*CCH*Hh*Ww];
__device__ float g_bufB[NB*CCH*Hh*Ww];
__device__ unsigned char g_pre[NB*Hh*Ww];
__device__ unsigned char g_alive[NB*Hh*Ww];

__device__ __forceinline__ ULL pk2(float a, float b){
    ULL r; asm("mov.b64 %0, {%1,%2};" : "=l"(r) : "f"(a), "f"(b)); return r;
}
__device__ __forceinline__ void fma2(ULL &d, ULL a, ULL b){
    asm("fma.rn.f32x2 %0, %1, %2, %0;" : "+l"(d) : "l"(a), "l"(b));
}
__device__ __forceinline__ float lo2(ULL v){ return __uint_as_float((unsigned)v); }
__device__ __forceinline__ float hi2(ULL v){ return __uint_as_float((unsigned)(v>>32)); }
__device__ __forceinline__ ULL relu2(ULL v){
    return pk2(fmaxf(lo2(v), 0.f), fmaxf(hi2(v), 0.f));
}

__global__ void init_kernel(const float* __restrict__ inp){
    int p = blockIdx.x*blockDim.x + threadIdx.x;
    const int total = NB*CCH*Hh*Ww;
    if (p >= total) return;
    int hw = p % (Hh*Ww);
    int c  = (p / (Hh*Ww)) % CCH;
    int n  = p / (CCH*Hh*Ww);
    float v;
    if (c == 0)       v = 1.0f - inp[(n*10 + 0)*Hh*Ww + hw];
    else if (c <= 10) v = inp[(n*10 + (c-1))*Hh*Ww + hw];
    else              v = 0.0f;
    g_bufA[p] = v;
    if (c == 0) g_alive[n*Hh*Ww + hw] = 1;
}

// smem ULL layout:
//   sw1:  [0, 2304)              w1 splatted [k][o]
//   sw2:  [2304, 3072)           w2 splatted [o][j]
//   sp:   [3072, 6144)           perc [48][64]; rows 16..47 reused as H rows 16..47
//   hlo:  [6144, 7168)           H rows 0..15 [16][64]
//   sc:   floats @ ULL 7168      16*10*19 floats
//   sa:   bytes after sc         18*10 alive tile
__global__ void __launch_bounds__(256, 3)
step_kernel(const float* __restrict__ w1, const float* __restrict__ w2, int parity)
{
    extern __shared__ ULL smem_u[];
    ULL* sw1 = smem_u;
    ULL* sw2 = smem_u + 2304;
    ULL* sp  = smem_u + 3072;
    ULL* hlo = smem_u + 6144;
    float* sc = (float*)(smem_u + 7168);
    unsigned char* sa = (unsigned char*)(sc + CCH*IH*IWP);

    const float* __restrict__ src = parity ? g_bufB : g_bufA;
    float* __restrict__ dst       = parity ? g_bufA : g_bufB;

    const int tid = threadIdx.x;
    const int n = blockIdx.z;
    const int gx0 = blockIdx.x*TW, gy0 = blockIdx.y*TH;

    // ---- stage 0: weights + alive tile ----
    for (int i = tid; i < 48*48; i += 256) {
        int k = i / 48, o = i % 48;
        float w = w1[o*48 + k];
        sw1[i] = pk2(w, w);
    }
    for (int i = tid; i < 48*16; i += 256) {
        int o = i >> 4, j = i & 15;
        float w = w2[j*48 + o];
        sw2[i] = pk2(w, w);
    }
    for (int i = tid; i < IW*IH; i += 256) {
        int sx = i % IW, sy = i / IW;
        int gx = gx0 + sx - 1, gy = gy0 + sy - 1;
        unsigned char a = 0;
        if (gx >= 0 && gx < Ww && gy >= 0 && gy < Hh)
            a = g_alive[(n*Hh + gy)*Ww + gx];
        sa[i] = a;
    }
    __syncthreads();
    // masked cell tile
    for (int i = tid; i < CCH*IH*IW; i += 256) {
        int sx = i % IW;
        int t  = i / IW;
        int sy = t % IH;
        int c  = t / IH;
        int gx = gx0 + sx - 1, gy = gy0 + sy - 1;
        float v = 0.0f;
        if (gx >= 0 && gx < Ww && gy >= 0 && gy < Hh && sa[sy*IW + sx])
            v = src[(((size_t)n*CCH + c)*Hh + gy)*Ww + gx];
        sc[(c*IH + sy)*IWP + sx] = v;
    }
    __syncthreads();

    // ---- stage 1: perception -> sp (4 threads per pair, 4 channels each) ----
    {
        const int pair = tid & 63;
        const int q    = tid >> 6;       // 0..3
        const int py = pair >> 3, px2 = pair & 7;
        const int sy = py + 1, sx = 2*px2 + 1;
        #pragma unroll
        for (int cc = 0; cc < 4; cc++) {
            int c = 4*q + cc;
            const float* b0 = sc + (c*IH + (sy-1))*IWP + (sx-1);
            const float* b1 = b0 + IWP;
            const float* b2 = b1 + IWP;
            float a0=b0[0],a1=b0[1],a2=b0[2],a3=b0[3];
            float m0=b1[0],m1=b1[1],m2=b1[2],m3=b1[3];
            float q0=b2[0],q1=b2[1],q2=b2[2],q3=b2[3];
            float gxl = ((a2 - a0) + 2.f*(m2 - m0) + (q2 - q0)) * 0.125f;
            float gxh = ((a3 - a1) + 2.f*(m3 - m1) + (q3 - q1)) * 0.125f;
            float gyl = ((q0 - a0) + 2.f*(q1 - a1) + (q2 - a2)) * 0.125f;
            float gyh = ((q1 - a1) + 2.f*(q2 - a2) + (q3 - a3)) * 0.125f;
            sp[c*NPAIR + pair]        = pk2(m1, m2);
            sp[(16 + c)*NPAIR + pair] = pk2(gxl, gxh);
            sp[(32 + c)*NPAIR + pair] = pk2(gyl, gyh);
            if (c == 0) {
                float t0 = fmaxf(fmaxf(a0,a1),a2);
                float t1 = fmaxf(fmaxf(m0,m1),m2);
                float t2 = fmaxf(fmaxf(q0,q1),q2);
                float pl = fmaxf(fmaxf(t0,t1),t2);
                float u0 = fmaxf(fmaxf(a1,a2),a3);
                float u1 = fmaxf(fmaxf(m1,m2),m3);
                float u2 = fmaxf(fmaxf(q1,q2),q3);
                float ph = fmaxf(fmaxf(u0,u1),u2);
                uchar2 pm;
                pm.x = (pl > 0.1f) ? 1 : 0;
                pm.y = (ph > 0.1f) ? 1 : 0;
                *reinterpret_cast<uchar2*>(g_pre + (n*Hh + gy0 + py)*Ww + gx0 + 2*px2) = pm;
            }
        }
    }
    __syncthreads();

    // ---- GEMM1: H = relu(W1 * perc), thread = (pair-lane g, o-block b of 6) ----
    {
        const int g = tid & 31;   // pairs g, g+32
        const int b = tid >> 5;   // o = 6b .. 6b+5
        ULL acc[2][6];
        #pragma unroll
        for (int i = 0; i < 2; i++)
            #pragma unroll
            for (int j = 0; j < 6; j++) acc[i][j] = 0ull;

        const ULL* wbase = sw1 + 6*b;
        // software pipeline depth 2
        ULL p0n = sp[g];
        ULL p1n = sp[g + 32];
        ulonglong2 wAn = *reinterpret_cast<const ulonglong2*>(wbase);
        ulonglong2 wBn = *reinterpret_cast<const ulonglong2*>(wbase + 2);
        ulonglong2 wCn = *reinterpret_cast<const ulonglong2*>(wbase + 4);
        #pragma unroll 8
        for (int k = 0; k < 48; k++) {
            ULL p0 = p0n, p1 = p1n;
            ulonglong2 wA = wAn, wB = wBn, wC = wCn;
            int kn = (k < 47) ? (k + 1) : 47;
            p0n = sp[kn*NPAIR + g];
            p1n = sp[kn*NPAIR + g + 32];
            const ULL* wr = wbase + kn*48;
            wAn = *reinterpret_cast<const ulonglong2*>(wr);
            wBn = *reinterpret_cast<const ulonglong2*>(wr + 2);
            wCn = *reinterpret_cast<const ulonglong2*>(wr + 4);
            fma2(acc[0][0], p0, wA.x); fma2(acc[1][0], p1, wA.x);
            fma2(acc[0][1], p0, wA.y); fma2(acc[1][1], p1, wA.y);
            fma2(acc[0][2], p0, wB.x); fma2(acc[1][2], p1, wB.x);
            fma2(acc[0][3], p0, wB.y); fma2(acc[1][3], p1, wB.y);
            fma2(acc[0][4], p0, wC.x); fma2(acc[1][4], p1, wC.x);
            fma2(acc[0][5], p0, wC.y); fma2(acc[1][5], p1, wC.y);
        }
        __syncthreads();   // all sp reads done before H overwrites rows 16..47
        #pragma unroll
        for (int oo = 0; oo < 6; oo++) {
            int o = 6*b + oo;
            ULL* hr = (o < 16) ? (hlo + o*NPAIR) : (sp + o*NPAIR);
            hr[g]      = relu2(acc[0][oo]);
            hr[g + 32] = relu2(acc[1][oo]);
        }
    }
    __syncthreads();

    // ---- GEMM2: cur = W2 * H + cell, thread = (pair g2, j-block jb of 4) ----
    {
        const int g2 = tid & 63;
        const int jb = tid >> 6;   // j = 4jb .. 4jb+3
        ULL c0[4];
        #pragma unroll
        for (int jj = 0; jj < 4; jj++)
            c0[jj] = sp[(4*jb + jj)*NPAIR + g2];   // residual (cell rows preserved)

        // pipeline depth 2
        const ULL* hr0 = hlo;  // o=0 < 16
        ULL hn = hr0[g2];
        ulonglong2 wAn = *reinterpret_cast<const ulonglong2*>(sw2 + 4*jb);
        ulonglong2 wBn = *reinterpret_cast<const ulonglong2*>(sw2 + 4*jb + 2);
        #pragma unroll 8
        for (int o = 0; o < 48; o++) {
            ULL h = hn;
            ulonglong2 wA = wAn, wB = wBn;
            int on = (o < 47) ? (o + 1) : 47;
            const ULL* hrn = (on < 16) ? (hlo + on*NPAIR) : (sp + on*NPAIR);
            hn = hrn[g2];
            const ULL* wr = sw2 + on*16 + 4*jb;
            wAn = *reinterpret_cast<const ulonglong2*>(wr);
            wBn = *reinterpret_cast<const ulonglong2*>(wr + 2);
            fma2(c0[0], h, wA.x); fma2(c0[1], h, wA.y);
            fma2(c0[2], h, wB.x); fma2(c0[3], h, wB.y);
        }
        // store
        const int py = g2 >> 3, px2 = g2 & 7;
        const int gy = gy0 + py, gx = gx0 + 2*px2;
        #pragma unroll
        for (int jj = 0; jj < 4; jj++) {
            int j = 4*jb + jj;
            *reinterpret_cast<ULL*>(dst + (((size_t)n*CCH + j)*Hh + gy)*Ww + gx) = c0[jj];
        }
    }
}

// post mask (3x3 maxpool of new cur ch0) & alive byte; last iter writes output.
__global__ void alive_kernel(float* __restrict__ outfinal, int parity, int writeOut)
{
    const float* __restrict__ cur = parity ? g_bufA : g_bufB;
    int p = blockIdx.x*blockDim.x + threadIdx.x;
    if (p >= NB*Hh*Ww) return;
    int x = p % Ww;
    int y = (p / Ww) % Hh;
    int n = p / (Hh*Ww);
    const float* c0 = cur + (size_t)n*CCH*Hh*Ww;
    float m = -1e30f;
    #pragma unroll
    for (int dy = -1; dy <= 1; dy++) {
        int yy = y + dy;
        if (yy < 0 || yy >= Hh) continue;
        const float* row = c0 + yy*Ww;
        #pragma unroll
        for (int dx = -1; dx <= 1; dx++) {
            int xx = x + dx;
            if (xx < 0 || xx >= Ww) continue;
            m = fmaxf(m, row[xx]);
        }
    }
    bool alive = (m > 0.1f) && (g_pre[p] != 0);
    g_alive[p] = alive ? 1 : 0;
    if (writeOut) {
        size_t base = ((size_t)n*CCH)*Hh*Ww + (size_t)y*Ww + x;
        #pragma unroll
        for (int c = 1; c <= 10; c++) {
            float v = alive ? cur[base + (size_t)c*Hh*Ww] : 0.0f;
            outfinal[(((size_t)n*10 + (c-1))*Hh + y)*Ww + x] = v;
        }
    }
}

extern "C" void kernel_launch(void* const* d_in, const int* in_sizes, int n_in,
                              void* d_out, int out_size)
{
    const float *inp = nullptr, *w1 = nullptr, *w2 = nullptr;
    for (int i = 0; i < n_in; i++) {
        if (in_sizes[i] == 48*48)      w1 = (const float*)d_in[i];
        else if (in_sizes[i] == 16*48) w2 = (const float*)d_in[i];
        else                           inp = (const float*)d_in[i];
    }
    float* out = (float*)d_out;

    // 7168 ULL + 3040 floats + 180 bytes
    const int smemBytes = 7168*8 + CCH*IH*IWP*4 + IW*IH + 64;  // ~69.7 KB
    cudaFuncSetAttribute(step_kernel, cudaFuncAttributeMaxDynamicSharedMemorySize, smemBytes);

    init_kernel<<<(NB*CCH*Hh*Ww + 255)/256, 256>>>(inp);

    dim3 g1(Ww/TW, Hh/TH, NB);   // (8, 16, 32) = 4096
    const int g2 = (NB*Hh*Ww + 255)/256;
    for (int it = 0; it < NITER; it++) {
        int parity = it & 1;
        step_kernel<<<g1, 256, smemBytes>>>(w1, w2, parity);
        alive_kernel<<<g2, 256>>>(out, parity, (it == NITER-1) ? 1 : 0);
    }
}

// round 7
// speedup vs baseline: 1.0110x; 1.0110x over previous
#include <cuda_runtime.h>

#define Hh 128
#define Ww 128
#define NB 32
#define CCH 16
#define NITER 30

#define TW 16
#define TH 8
#define IW 18
#define IH 10
#define IWP 19
#define NPAIR 64          // pairs per tile
#define NTILES 4096       // (128/16)*(128/8)*32
#define NCTA 444          // 148 SMs * 3

typedef unsigned long long ULL;

// persistent state — double buffered (halo race avoidance across iterations)
__device__ float g_bufA[NB*CCH*Hh*Ww];
__device__ float g_bufB[NB*CCH*Hh*Ww];
__device__ unsigned char g_pre[NB*Hh*Ww];
__device__ unsigned char g_alive[NB*Hh*Ww];

__device__ __forceinline__ ULL pk2(float a, float b){
    ULL r; asm("mov.b64 %0, {%1,%2};" : "=l"(r) : "f"(a), "f"(b)); return r;
}
__device__ __forceinline__ void fma2(ULL &d, ULL a, ULL b){
    asm("fma.rn.f32x2 %0, %1, %2, %0;" : "+l"(d) : "l"(a), "l"(b));
}
__device__ __forceinline__ float lo2(ULL v){ return __uint_as_float((unsigned)v); }
__device__ __forceinline__ float hi2(ULL v){ return __uint_as_float((unsigned)(v>>32)); }
__device__ __forceinline__ ULL relu2(ULL v){
    return pk2(fmaxf(lo2(v), 0.f), fmaxf(hi2(v), 0.f));
}

__global__ void init_kernel(const float* __restrict__ inp){
    int p = blockIdx.x*blockDim.x + threadIdx.x;
    const int total = NB*CCH*Hh*Ww;
    if (p >= total) return;
    int hw = p % (Hh*Ww);
    int c  = (p / (Hh*Ww)) % CCH;
    int n  = p / (CCH*Hh*Ww);
    float v;
    if (c == 0)       v = 1.0f - inp[(n*10 + 0)*Hh*Ww + hw];
    else if (c <= 10) v = inp[(n*10 + (c-1))*Hh*Ww + hw];
    else              v = 0.0f;
    g_bufA[p] = v;
    if (c == 0) g_alive[n*Hh*Ww + hw] = 1;
}

// smem ULL layout:
//   sw1:  [0, 2304)        w1 splatted [k][o]        (loaded once per CTA)
//   sw2:  [2304, 3072)     w2 splatted [o][j]
//   sp:   [3072, 6144)     perc [48][64]; rows 16..47 reused as H rows 16..47
//   hlo:  [6144, 7168)     H rows 0..15 [16][64]
//   sc:   floats @ 7168    16*10*19 cell tile
__global__ void __launch_bounds__(256, 3)
step_kernel(const float* __restrict__ w1, const float* __restrict__ w2, int parity)
{
    extern __shared__ ULL smem_u[];
    ULL* sw1 = smem_u;
    ULL* sw2 = smem_u + 2304;
    ULL* sp  = smem_u + 3072;
    ULL* hlo = smem_u + 6144;
    float* sc = (float*)(smem_u + 7168);

    const float* __restrict__ src = parity ? g_bufB : g_bufA;
    float* __restrict__ dst       = parity ? g_bufA : g_bufB;

    const int tid = threadIdx.x;

    // ---- stage weights ONCE per CTA ----
    for (int i = tid; i < 48*48; i += 256) {
        int k = i / 48, o = i % 48;
        float w = w1[o*48 + k];
        sw1[i] = pk2(w, w);
    }
    for (int i = tid; i < 48*16; i += 256) {
        int o = i >> 4, j = i & 15;
        float w = w2[j*48 + o];
        sw2[i] = pk2(w, w);
    }
    // (first in-loop barrier orders these writes before any read)

    #pragma unroll 1
    for (int tile = blockIdx.x; tile < NTILES; tile += NCTA) {
        const int n   = tile >> 7;          // 128 tiles per image
        const int rem = tile & 127;
        const int gy0 = (rem >> 3) * TH;
        const int gx0 = (rem & 7) * TW;

        // ---- stage cell tile (masked, zero-padded halo); overlaps prev GEMM2 ----
        const unsigned char* arow = g_alive + n*Hh*Ww;
        for (int i = tid; i < CCH*IH*IW; i += 256) {
            int sx = i % IW;
            int t  = i / IW;
            int sy = t % IH;
            int c  = t / IH;
            int gx = gx0 + sx - 1, gy = gy0 + sy - 1;
            float v = 0.0f;
            if ((unsigned)gx < (unsigned)Ww && (unsigned)gy < (unsigned)Hh) {
                int hw = gy*Ww + gx;
                if (arow[hw])
                    v = src[(size_t)(n*CCH + c)*(Hh*Ww) + hw];
            }
            sc[(c*IH + sy)*IWP + sx] = v;
        }
        __syncthreads();   // orders: prev GEMM2 sp/hlo reads, sc writes, weight writes

        // ---- perception -> sp (4 threads per pair, 4 channels each) ----
        {
            const int pair = tid & 63;
            const int q    = tid >> 6;
            const int py = pair >> 3, px2 = pair & 7;
            const int sy = py + 1, sx = 2*px2 + 1;
            #pragma unroll
            for (int cc = 0; cc < 4; cc++) {
                int c = 4*q + cc;
                const float* b0 = sc + (c*IH + (sy-1))*IWP + (sx-1);
                const float* b1 = b0 + IWP;
                const float* b2 = b1 + IWP;
                float a0=b0[0],a1=b0[1],a2=b0[2],a3=b0[3];
                float m0=b1[0],m1=b1[1],m2=b1[2],m3=b1[3];
                float q0=b2[0],q1=b2[1],q2=b2[2],q3=b2[3];
                float gxl = ((a2 - a0) + 2.f*(m2 - m0) + (q2 - q0)) * 0.125f;
                float gxh = ((a3 - a1) + 2.f*(m3 - m1) + (q3 - q1)) * 0.125f;
                float gyl = ((q0 - a0) + 2.f*(q1 - a1) + (q2 - a2)) * 0.125f;
                float gyh = ((q1 - a1) + 2.f*(q2 - a2) + (q3 - a3)) * 0.125f;
                sp[c*NPAIR + pair]        = pk2(m1, m2);
                sp[(16 + c)*NPAIR + pair] = pk2(gxl, gxh);
                sp[(32 + c)*NPAIR + pair] = pk2(gyl, gyh);
                if (c == 0) {
                    float t0 = fmaxf(fmaxf(a0,a1),a2);
                    float t1 = fmaxf(fmaxf(m0,m1),m2);
                    float t2 = fmaxf(fmaxf(q0,q1),q2);
                    float pl = fmaxf(fmaxf(t0,t1),t2);
                    float u0 = fmaxf(fmaxf(a1,a2),a3);
                    float u1 = fmaxf(fmaxf(m1,m2),m3);
                    float u2 = fmaxf(fmaxf(q1,q2),q3);
                    float ph = fmaxf(fmaxf(u0,u1),u2);
                    uchar2 pm;
                    pm.x = (pl > 0.1f) ? 1 : 0;
                    pm.y = (ph > 0.1f) ? 1 : 0;
                    *reinterpret_cast<uchar2*>(g_pre + (n*Hh + gy0 + py)*Ww + gx0 + 2*px2) = pm;
                }
            }
        }
        __syncthreads();

        // ---- GEMM1: H = relu(W1 * perc); thread = (pair-lane g, o-block b of 6) ----
        {
            const int g = tid & 31;
            const int b = tid >> 5;
            ULL acc[2][6];
            #pragma unroll
            for (int i = 0; i < 2; i++)
                #pragma unroll
                for (int j = 0; j < 6; j++) acc[i][j] = 0ull;

            const ULL* pp = sp + g;
            const ULL* wp = sw1 + 6*b;
            ULL p0 = pp[0], p1 = pp[32];
            #pragma unroll 4
            for (int k = 0; k < 47; k++) {
                ULL np0 = pp[64], np1 = pp[96];          // prefetch next k
                ulonglong2 wA = *reinterpret_cast<const ulonglong2*>(wp);
                ulonglong2 wB = *reinterpret_cast<const ulonglong2*>(wp + 2);
                ulonglong2 wC = *reinterpret_cast<const ulonglong2*>(wp + 4);
                fma2(acc[0][0], p0, wA.x); fma2(acc[1][0], p1, wA.x);
                fma2(acc[0][1], p0, wA.y); fma2(acc[1][1], p1, wA.y);
                fma2(acc[0][2], p0, wB.x); fma2(acc[1][2], p1, wB.x);
                fma2(acc[0][3], p0, wB.y); fma2(acc[1][3], p1, wB.y);
                fma2(acc[0][4], p0, wC.x); fma2(acc[1][4], p1, wC.x);
                fma2(acc[0][5], p0, wC.y); fma2(acc[1][5], p1, wC.y);
                p0 = np0; p1 = np1;
                pp += 64; wp += 48;
            }
            {   // peeled tail k=47
                ulonglong2 wA = *reinterpret_cast<const ulonglong2*>(wp);
                ulonglong2 wB = *reinterpret_cast<const ulonglong2*>(wp + 2);
                ulonglong2 wC = *reinterpret_cast<const ulonglong2*>(wp + 4);
                fma2(acc[0][0], p0, wA.x); fma2(acc[1][0], p1, wA.x);
                fma2(acc[0][1], p0, wA.y); fma2(acc[1][1], p1, wA.y);
                fma2(acc[0][2], p0, wB.x); fma2(acc[1][2], p1, wB.x);
                fma2(acc[0][3], p0, wB.y); fma2(acc[1][3], p1, wB.y);
                fma2(acc[0][4], p0, wC.x); fma2(acc[1][4], p1, wC.x);
                fma2(acc[0][5], p0, wC.y); fma2(acc[1][5], p1, wC.y);
            }
            __syncthreads();   // all sp reads done before H overwrites rows 16..47
            #pragma unroll
            for (int oo = 0; oo < 6; oo++) {
                int o = 6*b + oo;
                ULL* hr = (o < 16) ? (hlo + o*NPAIR) : (sp + o*NPAIR);
                hr[g]      = relu2(acc[0][oo]);
                hr[g + 32] = relu2(acc[1][oo]);
            }
        }
        __syncthreads();

        // ---- GEMM2: cur = W2 * H + cell; thread = (pair g2, j-block jb of 4) ----
        {
            const int g2 = tid & 63;
            const int jb = tid >> 6;
            ULL c0[4];
            {
                const ULL* cellp = sp + 4*jb*NPAIR + g2;
                c0[0] = cellp[0];
                c0[1] = cellp[NPAIR];
                c0[2] = cellp[2*NPAIR];
                c0[3] = cellp[3*NPAIR];
            }
            const ULL* wr = sw2 + 4*jb;
            const ULL* hp = hlo + g2;
            #pragma unroll 8
            for (int o = 0; o < 16; o++) {
                ULL h = hp[0];
                ulonglong2 wA = *reinterpret_cast<const ulonglong2*>(wr);
                ulonglong2 wB = *reinterpret_cast<const ulonglong2*>(wr + 2);
                fma2(c0[0], h, wA.x); fma2(c0[1], h, wA.y);
                fma2(c0[2], h, wB.x); fma2(c0[3], h, wB.y);
                hp += NPAIR; wr += 16;
            }
            hp = sp + 16*NPAIR + g2;
            #pragma unroll 8
            for (int o = 16; o < 48; o++) {
                ULL h = hp[0];
                ulonglong2 wA = *reinterpret_cast<const ulonglong2*>(wr);
                ulonglong2 wB = *reinterpret_cast<const ulonglong2*>(wr + 2);
                fma2(c0[0], h, wA.x); fma2(c0[1], h, wA.y);
                fma2(c0[2], h, wB.x); fma2(c0[3], h, wB.y);
                hp += NPAIR; wr += 16;
            }
            const int py = g2 >> 3, px2 = g2 & 7;
            const int gy = gy0 + py, gx = gx0 + 2*px2;
            float* dbase = dst + ((size_t)(n*CCH + 4*jb)*Hh + gy)*Ww + gx;
            *reinterpret_cast<ULL*>(dbase)              = c0[0];
            *reinterpret_cast<ULL*>(dbase + Hh*Ww)      = c0[1];
            *reinterpret_cast<ULL*>(dbase + 2*Hh*Ww)    = c0[2];
            *reinterpret_cast<ULL*>(dbase + 3*Hh*Ww)    = c0[3];
        }
        // no barrier here: next tile's first barrier orders GEMM2 reads vs sp rewrite
    }
}

// post mask (3x3 maxpool of new cur ch0) & alive byte; last iter writes output.
__global__ void alive_kernel(float* __restrict__ outfinal, int parity, int writeOut)
{
    const float* __restrict__ cur = parity ? g_bufA : g_bufB;
    int p = blockIdx.x*blockDim.x + threadIdx.x;
    if (p >= NB*Hh*Ww) return;
    int x = p % Ww;
    int y = (p / Ww) % Hh;
    int n = p / (Hh*Ww);
    const float* c0 = cur + (size_t)n*CCH*Hh*Ww;
    float m = -1e30f;
    #pragma unroll
    for (int dy = -1; dy <= 1; dy++) {
        int yy = y + dy;
        if (yy < 0 || yy >= Hh) continue;
        const float* row = c0 + yy*Ww;
        #pragma unroll
        for (int dx = -1; dx <= 1; dx++) {
            int xx = x + dx;
            if (xx < 0 || xx >= Ww) continue;
            m = fmaxf(m, row[xx]);
        }
    }
    bool alive = (m > 0.1f) && (g_pre[p] != 0);
    g_alive[p] = alive ? 1 : 0;
    if (writeOut) {
        size_t base = ((size_t)n*CCH)*Hh*Ww + (size_t)y*Ww + x;
        #pragma unroll
        for (int c = 1; c <= 10; c++) {
            float v = alive ? cur[base + (size_t)c*Hh*Ww] : 0.0f;
            outfinal[(((size_t)n*10 + (c-1))*Hh + y)*Ww + x] = v;
        }
    }
}

extern "C" void kernel_launch(void* const* d_in, const int* in_sizes, int n_in,
                              void* d_out, int out_size)
{
    const float *inp = nullptr, *w1 = nullptr, *w2 = nullptr;
    for (int i = 0; i < n_in; i++) {
        if (in_sizes[i] == 48*48)      w1 = (const float*)d_in[i];
        else if (in_sizes[i] == 16*48) w2 = (const float*)d_in[i];
        else                           inp = (const float*)d_in[i];
    }
    float* out = (float*)d_out;

    const int smemBytes = 7168*8 + CCH*IH*IWP*4 + 64;  // 57344 + 12160 + 64 = 69568
    cudaFuncSetAttribute(step_kernel, cudaFuncAttributeMaxDynamicSharedMemorySize, smemBytes);

    init_kernel<<<(NB*CCH*Hh*Ww + 255)/256, 256>>>(inp);

    const int g2 = (NB*Hh*Ww + 255)/256;
    for (int it = 0; it < NITER; it++) {
        int parity = it & 1;
        step_kernel<<<NCTA, 256, smemBytes>>>(w1, w2, parity);
        alive_kernel<<<g2, 256>>>(out, parity, (it == NITER-1) ? 1 : 0);
    }
}

// round 8
// speedup vs baseline: 1.1009x; 1.0889x over previous
#include <cuda_runtime.h>

#define Hh 128
#define Ww 128
#define NB 32
#define CCH 16
#define NITER 30

#define TW 16
#define TH 16
#define IW 18
#define IH 18
#define IWP 20            // even -> float2-aligned rows
#define NPAIR 128         // pairs per tile (16x16 px)
#define NTILES 2048       // 64 tiles/image * 32
#define NCTA 296          // 148 SMs * 2

typedef unsigned long long ULL;

// persistent state — double buffered (halo race avoidance across iterations)
__device__ float g_bufA[NB*CCH*Hh*Ww];
__device__ float g_bufB[NB*CCH*Hh*Ww];
__device__ unsigned char g_pre[NB*Hh*Ww];
__device__ unsigned char g_alive[NB*Hh*Ww];

__device__ __forceinline__ ULL pk2(float a, float b){
    ULL r; asm("mov.b64 %0, {%1,%2};" : "=l"(r) : "f"(a), "f"(b)); return r;
}
__device__ __forceinline__ void fma2(ULL &d, ULL a, ULL b){
    asm("fma.rn.f32x2 %0, %1, %2, %0;" : "+l"(d) : "l"(a), "l"(b));
}
__device__ __forceinline__ float lo2(ULL v){ return __uint_as_float((unsigned)v); }
__device__ __forceinline__ float hi2(ULL v){ return __uint_as_float((unsigned)(v>>32)); }
__device__ __forceinline__ ULL relu2(ULL v){
    return pk2(fmaxf(lo2(v), 0.f), fmaxf(hi2(v), 0.f));
}

__global__ void init_kernel(const float* __restrict__ inp){
    int p = blockIdx.x*blockDim.x + threadIdx.x;
    const int total = NB*CCH*Hh*Ww;
    if (p >= total) return;
    int hw = p % (Hh*Ww);
    int c  = (p / (Hh*Ww)) % CCH;
    int n  = p / (CCH*Hh*Ww);
    float v;
    if (c == 0)       v = 1.0f - inp[(n*10 + 0)*Hh*Ww + hw];
    else if (c <= 10) v = inp[(n*10 + (c-1))*Hh*Ww + hw];
    else              v = 0.0f;
    g_bufA[p] = v;
    if (c == 0) g_alive[n*Hh*Ww + hw] = 1;
}

// smem ULL layout:
//   sw1:  [0, 2304)        w1 splatted [k][o]   (staged once per CTA)
//   sw2:  [2304, 3072)     w2 splatted [o][j]
//   sp:   [3072, 9216)     perc [48][128]; rows 16..47 reused as H rows 16..47
//   union @ 9216 (2880 ULL):
//     sc:  16*18*20 floats (cell tile; dead after perception)
//     hlo: H rows 0..15 [16][128]  (written at end of GEMM1)
__global__ void __launch_bounds__(256, 2)
step_kernel(const float* __restrict__ w1, const float* __restrict__ w2, int parity)
{
    extern __shared__ ULL smem_u[];
    ULL* sw1 = smem_u;
    ULL* sw2 = smem_u + 2304;
    ULL* sp  = smem_u + 3072;
    ULL* hlo = smem_u + 9216;
    float* sc = (float*)(smem_u + 9216);

    const float* __restrict__ src = parity ? g_bufB : g_bufA;
    float* __restrict__ dst       = parity ? g_bufA : g_bufB;

    const int tid = threadIdx.x;

    // ---- stage weights ONCE per CTA ----
    for (int i = tid; i < 48*48; i += 256) {
        int k = i / 48, o = i % 48;
        float w = w1[o*48 + k];
        sw1[i] = pk2(w, w);
    }
    for (int i = tid; i < 48*16; i += 256) {
        int o = i >> 4, j = i & 15;
        float w = w2[j*48 + o];
        sw2[i] = pk2(w, w);
    }

    #pragma unroll 1
    for (int tile = blockIdx.x; tile < NTILES; tile += NCTA) {
        const int n   = tile >> 6;          // 64 tiles per image
        const int rem = tile & 63;
        const int gy0 = (rem >> 3) * TH;
        const int gx0 = (rem & 7) * TW;

        // ---- stage cell tile (masked, zero-padded halo) ----
        const unsigned char* arow = g_alive + n*Hh*Ww;
        for (int i = tid; i < CCH*IH*IW; i += 256) {
            int sx = i % IW;
            int t  = i / IW;
            int sy = t % IH;
            int c  = t / IH;
            int gx = gx0 + sx - 1, gy = gy0 + sy - 1;
            float v = 0.0f;
            if ((unsigned)gx < (unsigned)Ww && (unsigned)gy < (unsigned)Hh) {
                int hw = gy*Ww + gx;
                if (arow[hw])
                    v = src[(size_t)(n*CCH + c)*(Hh*Ww) + hw];
            }
            sc[(c*IH + sy)*IWP + sx] = v;
        }
        __syncthreads();

        // ---- perception -> sp (2 threads per pair, 8 channels each) ----
        {
            const int pair = tid & 127;
            const int q    = tid >> 7;           // 0..1
            const int py = pair >> 3, px2 = pair & 7;
            const int sy = py + 1;
            #pragma unroll
            for (int cc = 0; cc < 8; cc++) {
                int c = 8*q + cc;
                const float2* r0 = (const float2*)(sc + (c*IH + sy - 1)*IWP + 2*px2);
                const float2* r1 = (const float2*)((const float*)r0 + IWP);
                const float2* r2 = (const float2*)((const float*)r1 + IWP);
                float2 v00 = r0[0], v01 = r0[1];
                float2 v10 = r1[0], v11 = r1[1];
                float2 v20 = r2[0], v21 = r2[1];
                float a0=v00.x,a1=v00.y,a2=v01.x,a3=v01.y;
                float m0=v10.x,m1=v10.y,m2=v11.x,m3=v11.y;
                float q0=v20.x,q1=v20.y,q2=v21.x,q3=v21.y;
                float gxl = ((a2 - a0) + 2.f*(m2 - m0) + (q2 - q0)) * 0.125f;
                float gxh = ((a3 - a1) + 2.f*(m3 - m1) + (q3 - q1)) * 0.125f;
                float gyl = ((q0 - a0) + 2.f*(q1 - a1) + (q2 - a2)) * 0.125f;
                float gyh = ((q1 - a1) + 2.f*(q2 - a2) + (q3 - a3)) * 0.125f;
                sp[c*NPAIR + pair]        = pk2(m1, m2);
                sp[(16 + c)*NPAIR + pair] = pk2(gxl, gxh);
                sp[(32 + c)*NPAIR + pair] = pk2(gyl, gyh);
                if (c == 0) {
                    float t0 = fmaxf(fmaxf(a0,a1),a2);
                    float t1 = fmaxf(fmaxf(m0,m1),m2);
                    float t2 = fmaxf(fmaxf(q0,q1),q2);
                    float pl = fmaxf(fmaxf(t0,t1),t2);
                    float u0 = fmaxf(fmaxf(a1,a2),a3);
                    float u1 = fmaxf(fmaxf(m1,m2),m3);
                    float u2 = fmaxf(fmaxf(q1,q2),q3);
                    float ph = fmaxf(fmaxf(u0,u1),u2);
                    uchar2 pm;
                    pm.x = (pl > 0.1f) ? 1 : 0;
                    pm.y = (ph > 0.1f) ? 1 : 0;
                    *reinterpret_cast<uchar2*>(g_pre + (n*Hh + gy0 + py)*Ww + gx0 + 2*px2) = pm;
                }
            }
        }
        __syncthreads();

        // ---- GEMM1: H = relu(W1*perc); thread = (g in 64, ob in 4 of 12 o) ----
        {
            const int g  = tid & 63;     // pairs g, g+64
            const int ob = tid >> 6;     // o = 12*ob .. 12*ob+11
            ULL acc[2][12];
            #pragma unroll
            for (int i = 0; i < 2; i++)
                #pragma unroll
                for (int j = 0; j < 12; j++) acc[i][j] = 0ull;

            const ULL* pp = sp + g;
            const ULL* wp = sw1 + 12*ob;
            ULL p0 = pp[0], p1 = pp[64];
            #pragma unroll 4
            for (int k = 0; k < 47; k++) {
                ULL np0 = pp[128], np1 = pp[192];   // prefetch next k
                ulonglong2 w0 = *reinterpret_cast<const ulonglong2*>(wp);
                ulonglong2 w1v = *reinterpret_cast<const ulonglong2*>(wp + 2);
                ulonglong2 w2v = *reinterpret_cast<const ulonglong2*>(wp + 4);
                ulonglong2 w3 = *reinterpret_cast<const ulonglong2*>(wp + 6);
                ulonglong2 w4 = *reinterpret_cast<const ulonglong2*>(wp + 8);
                ulonglong2 w5 = *reinterpret_cast<const ulonglong2*>(wp + 10);
                fma2(acc[0][0],  p0, w0.x);  fma2(acc[1][0],  p1, w0.x);
                fma2(acc[0][1],  p0, w0.y);  fma2(acc[1][1],  p1, w0.y);
                fma2(acc[0][2],  p0, w1v.x); fma2(acc[1][2],  p1, w1v.x);
                fma2(acc[0][3],  p0, w1v.y); fma2(acc[1][3],  p1, w1v.y);
                fma2(acc[0][4],  p0, w2v.x); fma2(acc[1][4],  p1, w2v.x);
                fma2(acc[0][5],  p0, w2v.y); fma2(acc[1][5],  p1, w2v.y);
                fma2(acc[0][6],  p0, w3.x);  fma2(acc[1][6],  p1, w3.x);
                fma2(acc[0][7],  p0, w3.y);  fma2(acc[1][7],  p1, w3.y);
                fma2(acc[0][8],  p0, w4.x);  fma2(acc[1][8],  p1, w4.x);
                fma2(acc[0][9],  p0, w4.y);  fma2(acc[1][9],  p1, w4.y);
                fma2(acc[0][10], p0, w5.x);  fma2(acc[1][10], p1, w5.x);
                fma2(acc[0][11], p0, w5.y);  fma2(acc[1][11], p1, w5.y);
                p0 = np0; p1 = np1;
                pp += 128; wp += 48;
            }
            {   // peeled tail k = 47
                ulonglong2 w0 = *reinterpret_cast<const ulonglong2*>(wp);
                ulonglong2 w1v = *reinterpret_cast<const ulonglong2*>(wp + 2);
                ulonglong2 w2v = *reinterpret_cast<const ulonglong2*>(wp + 4);
                ulonglong2 w3 = *reinterpret_cast<const ulonglong2*>(wp + 6);
                ulonglong2 w4 = *reinterpret_cast<const ulonglong2*>(wp + 8);
                ulonglong2 w5 = *reinterpret_cast<const ulonglong2*>(wp + 10);
                fma2(acc[0][0],  p0, w0.x);  fma2(acc[1][0],  p1, w0.x);
                fma2(acc[0][1],  p0, w0.y);  fma2(acc[1][1],  p1, w0.y);
                fma2(acc[0][2],  p0, w1v.x); fma2(acc[1][2],  p1, w1v.x);
                fma2(acc[0][3],  p0, w1v.y); fma2(acc[1][3],  p1, w1v.y);
                fma2(acc[0][4],  p0, w2v.x); fma2(acc[1][4],  p1, w2v.x);
                fma2(acc[0][5],  p0, w2v.y); fma2(acc[1][5],  p1, w2v.y);
                fma2(acc[0][6],  p0, w3.x);  fma2(acc[1][6],  p1, w3.x);
                fma2(acc[0][7],  p0, w3.y);  fma2(acc[1][7],  p1, w3.y);
                fma2(acc[0][8],  p0, w4.x);  fma2(acc[1][8],  p1, w4.x);
                fma2(acc[0][9],  p0, w4.y);  fma2(acc[1][9],  p1, w4.y);
                fma2(acc[0][10], p0, w5.x);  fma2(acc[1][10], p1, w5.x);
                fma2(acc[0][11], p0, w5.y);  fma2(acc[1][11], p1, w5.y);
            }
            __syncthreads();   // sp reads done before H overwrites rows 16..47 / sc->hlo
            #pragma unroll
            for (int oo = 0; oo < 12; oo++) {
                int o = 12*ob + oo;
                ULL* hr = (o < 16) ? (hlo + o*NPAIR) : (sp + o*NPAIR);
                hr[g]      = relu2(acc[0][oo]);
                hr[g + 64] = relu2(acc[1][oo]);
            }
        }
        __syncthreads();

        // ---- GEMM2: cur = W2*H + cell; thread = (g2 in 64, jb in 4 of 4 j) ----
        {
            const int g2 = tid & 63;     // pairs g2, g2+64
            const int jb = tid >> 6;     // j = 4*jb .. 4*jb+3
            ULL c0[4], c1[4];
            {
                const ULL* cp = sp + 4*jb*NPAIR + g2;
                c0[0] = cp[0];       c1[0] = cp[64];
                c0[1] = cp[NPAIR];   c1[1] = cp[NPAIR+64];
                c0[2] = cp[2*NPAIR]; c1[2] = cp[2*NPAIR+64];
                c0[3] = cp[3*NPAIR]; c1[3] = cp[3*NPAIR+64];
            }
            const ULL* wr = sw2 + 4*jb;
            const ULL* hp = hlo + g2;
            #pragma unroll 8
            for (int o = 0; o < 16; o++) {
                ULL h0 = hp[0], h1 = hp[64];
                ulonglong2 wA = *reinterpret_cast<const ulonglong2*>(wr);
                ulonglong2 wB = *reinterpret_cast<const ulonglong2*>(wr + 2);
                fma2(c0[0], h0, wA.x); fma2(c0[1], h0, wA.y);
                fma2(c0[2], h0, wB.x); fma2(c0[3], h0, wB.y);
                fma2(c1[0], h1, wA.x); fma2(c1[1], h1, wA.y);
                fma2(c1[2], h1, wB.x); fma2(c1[3], h1, wB.y);
                hp += NPAIR; wr += 16;
            }
            hp = sp + 16*NPAIR + g2;
            #pragma unroll 8
            for (int o = 16; o < 48; o++) {
                ULL h0 = hp[0], h1 = hp[64];
                ulonglong2 wA = *reinterpret_cast<const ulonglong2*>(wr);
                ulonglong2 wB = *reinterpret_cast<const ulonglong2*>(wr + 2);
                fma2(c0[0], h0, wA.x); fma2(c0[1], h0, wA.y);
                fma2(c0[2], h0, wB.x); fma2(c0[3], h0, wB.y);
                fma2(c1[0], h1, wA.x); fma2(c1[1], h1, wA.y);
                fma2(c1[2], h1, wB.x); fma2(c1[3], h1, wB.y);
                hp += NPAIR; wr += 16;
            }
            // stores: pair p -> (py=p>>3, px2=p&7)
            {
                const int p0i = g2,      p1i = g2 + 64;
                const int gyA = gy0 + (p0i >> 3), gxA = gx0 + 2*(p0i & 7);
                const int gyB = gy0 + (p1i >> 3), gxB = gx0 + 2*(p1i & 7);
                float* dA = dst + ((size_t)(n*CCH + 4*jb)*Hh + gyA)*Ww + gxA;
                float* dB = dst + ((size_t)(n*CCH + 4*jb)*Hh + gyB)*Ww + gxB;
                *reinterpret_cast<ULL*>(dA)           = c0[0];
                *reinterpret_cast<ULL*>(dA + Hh*Ww)   = c0[1];
                *reinterpret_cast<ULL*>(dA + 2*Hh*Ww) = c0[2];
                *reinterpret_cast<ULL*>(dA + 3*Hh*Ww) = c0[3];
                *reinterpret_cast<ULL*>(dB)           = c1[0];
                *reinterpret_cast<ULL*>(dB + Hh*Ww)   = c1[1];
                *reinterpret_cast<ULL*>(dB + 2*Hh*Ww) = c1[2];
                *reinterpret_cast<ULL*>(dB + 3*Hh*Ww) = c1[3];
            }
        }
        __syncthreads();   // GEMM2 hlo/sp reads done before next tile's staging writes sc
    }
}

// post mask (3x3 maxpool of new cur ch0) & alive byte; last iter writes output.
__global__ void alive_kernel(float* __restrict__ outfinal, int parity, int writeOut)
{
    const float* __restrict__ cur = parity ? g_bufA : g_bufB;
    int p = blockIdx.x*blockDim.x + threadIdx.x;
    if (p >= NB*Hh*Ww) return;
    int x = p % Ww;
    int y = (p / Ww) % Hh;
    int n = p / (Hh*Ww);
    const float* c0 = cur + (size_t)n*CCH*Hh*Ww;
    float m = -1e30f;
    #pragma unroll
    for (int dy = -1; dy <= 1; dy++) {
        int yy = y + dy;
        if (yy < 0 || yy >= Hh) continue;
        const float* row = c0 + yy*Ww;
        #pragma unroll
        for (int dx = -1; dx <= 1; dx++) {
            int xx = x + dx;
            if (xx < 0 || xx >= Ww) continue;
            m = fmaxf(m, row[xx]);
        }
    }
    bool alive = (m > 0.1f) && (g_pre[p] != 0);
    g_alive[p] = alive ? 1 : 0;
    if (writeOut) {
        size_t base = ((size_t)n*CCH)*Hh*Ww + (size_t)y*Ww + x;
        #pragma unroll
        for (int c = 1; c <= 10; c++) {
            float v = alive ? cur[base + (size_t)c*Hh*Ww] : 0.0f;
            outfinal[(((size_t)n*10 + (c-1))*Hh + y)*Ww + x] = v;
        }
    }
}

extern "C" void kernel_launch(void* const* d_in, const int* in_sizes, int n_in,
                              void* d_out, int out_size)
{
    const float *inp = nullptr, *w1 = nullptr, *w2 = nullptr;
    for (int i = 0; i < n_in; i++) {
        if (in_sizes[i] == 48*48)      w1 = (const float*)d_in[i];
        else if (in_sizes[i] == 16*48) w2 = (const float*)d_in[i];
        else                           inp = (const float*)d_in[i];
    }
    float* out = (float*)d_out;

    // 9216 ULL + union(sc 5760 floats = 2880 ULL) = 12096 ULL = 96768 B
    const int smemBytes = 12096*8;
    cudaFuncSetAttribute(step_kernel, cudaFuncAttributeMaxDynamicSharedMemorySize, smemBytes);

    init_kernel<<<(NB*CCH*Hh*Ww + 255)/256, 256>>>(inp);

    const int g2 = (NB*Hh*Ww + 255)/256;
    for (int it = 0; it < NITER; it++) {
        int parity = it & 1;
        step_kernel<<<NCTA, 256, smemBytes>>>(w1, w2, parity);
        alive_kernel<<<g2, 256>>>(out, parity, (it == NITER-1) ? 1 : 0);
    }
}

// round 9
// speedup vs baseline: 1.2194x; 1.1077x over previous
#include <cuda_runtime.h>

#define Hh 128
#define Ww 128
#define NB 32
#define CCH 16
#define NITER 30

#define TW 16
#define TH 16
#define IW 18
#define IH 18
#define NPX 256           // pixels per tile
#define NTILES 2048
#define NCTA 444          // 148 * 3

typedef unsigned long long ULL;

__device__ float g_bufA[NB*CCH*Hh*Ww];
__device__ float g_bufB[NB*CCH*Hh*Ww];
__device__ unsigned char g_pre[NB*Hh*Ww];
__device__ unsigned char g_alive[NB*Hh*Ww];

__device__ __forceinline__ ULL pk2(float a, float b){
    ULL r; asm("mov.b64 %0, {%1,%2};" : "=l"(r) : "f"(a), "f"(b)); return r;
}
__device__ __forceinline__ void fma2(ULL &d, ULL a, ULL b){
    asm("fma.rn.f32x2 %0, %1, %2, %0;" : "+l"(d) : "l"(a), "l"(b));
}
__device__ __forceinline__ float lo2(ULL v){ return __uint_as_float((unsigned)v); }
__device__ __forceinline__ float hi2(ULL v){ return __uint_as_float((unsigned)(v>>32)); }

__global__ void init_kernel(const float* __restrict__ inp){
    int p = blockIdx.x*blockDim.x + threadIdx.x;
    const int total = NB*CCH*Hh*Ww;
    if (p >= total) return;
    int hw = p % (Hh*Ww);
    int c  = (p / (Hh*Ww)) % CCH;
    int n  = p / (CCH*Hh*Ww);
    float v;
    if (c == 0)       v = 1.0f - inp[(n*10 + 0)*Hh*Ww + hw];
    else if (c <= 10) v = inp[(n*10 + (c-1))*Hh*Ww + hw];
    else              v = 0.0f;
    g_bufA[p] = v;
    if (c == 0) g_alive[n*Hh*Ww + hw] = 1;
}

// smem float layout:
//   sw1f: [0, 2304)        w1 transposed [k][o] plain floats
//   sw2f: [2304, 3072)     w2 transposed [o][j]
//   spf:  [3072, 11264)    sobel rows [32][256] (gx c -> row c, gy c -> row 16+c);
//                          after GEMM1: H rows 0..31
//   scf:  [11264, 16448)   cell tile 16*18*18; after GEMM1: H rows 32..47 (first 4096)
__global__ void __launch_bounds__(256, 3)
step_kernel(const float* __restrict__ w1, const float* __restrict__ w2, int parity)
{
    extern __shared__ float smem_f[];
    float* sw1f = smem_f;
    float* sw2f = smem_f + 2304;
    float* spf  = smem_f + 3072;
    float* scf  = smem_f + 11264;

    const float* __restrict__ src = parity ? g_bufB : g_bufA;
    float* __restrict__ dst       = parity ? g_bufA : g_bufB;

    const int tid = threadIdx.x;

    // ---- stage weights ONCE per CTA (plain floats, transposed) ----
    for (int i = tid; i < 48*48; i += 256) {
        int k = i / 48, o = i % 48;
        sw1f[i] = w1[o*48 + k];
    }
    for (int i = tid; i < 48*16; i += 256) {
        int o = i >> 4, j = i & 15;
        sw2f[i] = w2[j*48 + o];
    }

    #pragma unroll 1
    for (int tile = blockIdx.x; tile < NTILES; tile += NCTA) {
        const int n   = tile >> 6;
        const int rem = tile & 63;
        const int gy0 = (rem >> 3) * TH;
        const int gx0 = (rem & 7) * TW;

        // ---- stage cell tile (masked, zero-padded halo) ----
        const unsigned char* arow = g_alive + n*Hh*Ww;
        for (int i = tid; i < CCH*IH*IW; i += 256) {
            int sx = i % IW;
            int t  = i / IW;
            int sy = t % IH;
            int c  = t / IH;
            int gx = gx0 + sx - 1, gy = gy0 + sy - 1;
            float v = 0.0f;
            if ((unsigned)gx < (unsigned)Ww && (unsigned)gy < (unsigned)Hh) {
                int hw = gy*Ww + gx;
                if (arow[hw])
                    v = src[(size_t)(n*CCH + c)*(Hh*Ww) + hw];
            }
            scf[(c*IH + sy)*IW + sx] = v;
        }
        __syncthreads();

        // ---- perception: sobel -> spf rows (cell stays in scf) ----
        {
            const int pair = tid & 127;          // 128 pixel-pairs
            const int q    = tid >> 7;           // 0..1 -> 8 channels each
            const int py = pair >> 3, px2 = pair & 7;
            const int sy = py + 1;
            #pragma unroll
            for (int cc = 0; cc < 8; cc++) {
                int c = 8*q + cc;
                const float2* r0 = (const float2*)(scf + (c*IH + sy - 1)*IW + 2*px2);
                const float2* r1 = (const float2*)((const float*)r0 + IW);
                const float2* r2 = (const float2*)((const float*)r1 + IW);
                float2 v00 = r0[0], v01 = r0[1];
                float2 v10 = r1[0], v11 = r1[1];
                float2 v20 = r2[0], v21 = r2[1];
                float a0=v00.x,a1=v00.y,a2=v01.x,a3=v01.y;
                float m0=v10.x,m1=v10.y,m2=v11.x,m3=v11.y;
                float q0=v20.x,q1=v20.y,q2=v21.x,q3=v21.y;
                float gxl = ((a2 - a0) + 2.f*(m2 - m0) + (q2 - q0)) * 0.125f;
                float gxh = ((a3 - a1) + 2.f*(m3 - m1) + (q3 - q1)) * 0.125f;
                float gyl = ((q0 - a0) + 2.f*(q1 - a1) + (q2 - a2)) * 0.125f;
                float gyh = ((q1 - a1) + 2.f*(q2 - a2) + (q3 - a3)) * 0.125f;
                *(float2*)(spf + c*NPX + 2*pair)        = make_float2(gxl, gxh);
                *(float2*)(spf + (16 + c)*NPX + 2*pair) = make_float2(gyl, gyh);
                if (c == 0) {
                    float t0 = fmaxf(fmaxf(a0,a1),a2);
                    float t1 = fmaxf(fmaxf(m0,m1),m2);
                    float t2 = fmaxf(fmaxf(q0,q1),q2);
                    float pl = fmaxf(fmaxf(t0,t1),t2);
                    float u0 = fmaxf(fmaxf(a1,a2),a3);
                    float u1 = fmaxf(fmaxf(m1,m2),m3);
                    float u2 = fmaxf(fmaxf(q1,q2),q3);
                    float ph = fmaxf(fmaxf(u0,u1),u2);
                    uchar2 pm;
                    pm.x = (pl > 0.1f) ? 1 : 0;
                    pm.y = (ph > 0.1f) ? 1 : 0;
                    *reinterpret_cast<uchar2*>(g_pre + (n*Hh + gy0 + py)*Ww + gx0 + 2*px2) = pm;
                }
            }
        }
        __syncthreads();

        // ---- GEMM1: H = relu(W1*perc); thread = (g in 64 px-lanes, ob of 12 o) ----
        {
            const int g  = tid & 63;     // px = g + 64m, m=0..3
            const int ob = tid >> 6;     // o = 12*ob .. 12*ob+11
            ULL acc[4][6];
            #pragma unroll
            for (int m = 0; m < 4; m++)
                #pragma unroll
                for (int j = 0; j < 6; j++) acc[m][j] = 0ull;

            int offm[4];
            #pragma unroll
            for (int m = 0; m < 4; m++) {
                int px = g + 64*m;
                offm[m] = ((px >> 4) + 1)*IW + (px & 15) + 1;
            }

            // part A: k = 0..15, cell from scf
            #pragma unroll 4
            for (int k = 0; k < 16; k++) {
                float p0 = scf[k*(IH*IW) + offm[0]];
                float p1 = scf[k*(IH*IW) + offm[1]];
                float p2 = scf[k*(IH*IW) + offm[2]];
                float p3 = scf[k*(IH*IW) + offm[3]];
                ULL s0 = pk2(p0,p0), s1 = pk2(p1,p1), s2 = pk2(p2,p2), s3 = pk2(p3,p3);
                const ulonglong2* wv = (const ulonglong2*)(sw1f + k*48 + 12*ob);
                ulonglong2 w0 = wv[0], w1v = wv[1], w2v = wv[2];
                fma2(acc[0][0], s0, w0.x);  fma2(acc[1][0], s1, w0.x);  fma2(acc[2][0], s2, w0.x);  fma2(acc[3][0], s3, w0.x);
                fma2(acc[0][1], s0, w0.y);  fma2(acc[1][1], s1, w0.y);  fma2(acc[2][1], s2, w0.y);  fma2(acc[3][1], s3, w0.y);
                fma2(acc[0][2], s0, w1v.x); fma2(acc[1][2], s1, w1v.x); fma2(acc[2][2], s2, w1v.x); fma2(acc[3][2], s3, w1v.x);
                fma2(acc[0][3], s0, w1v.y); fma2(acc[1][3], s1, w1v.y); fma2(acc[2][3], s2, w1v.y); fma2(acc[3][3], s3, w1v.y);
                fma2(acc[0][4], s0, w2v.x); fma2(acc[1][4], s1, w2v.x); fma2(acc[2][4], s2, w2v.x); fma2(acc[3][4], s3, w2v.x);
                fma2(acc[0][5], s0, w2v.y); fma2(acc[1][5], s1, w2v.y); fma2(acc[2][5], s2, w2v.y); fma2(acc[3][5], s3, w2v.y);
            }
            // part B: k = 16..47, sobel from spf rows 0..31
            #pragma unroll 4
            for (int k2 = 0; k2 < 32; k2++) {
                const float* pr = spf + k2*NPX + g;
                float p0 = pr[0], p1 = pr[64], p2 = pr[128], p3 = pr[192];
                ULL s0 = pk2(p0,p0), s1 = pk2(p1,p1), s2 = pk2(p2,p2), s3 = pk2(p3,p3);
                const ulonglong2* wv = (const ulonglong2*)(sw1f + (16 + k2)*48 + 12*ob);
                ulonglong2 w0 = wv[0], w1v = wv[1], w2v = wv[2];
                fma2(acc[0][0], s0, w0.x);  fma2(acc[1][0], s1, w0.x);  fma2(acc[2][0], s2, w0.x);  fma2(acc[3][0], s3, w0.x);
                fma2(acc[0][1], s0, w0.y);  fma2(acc[1][1], s1, w0.y);  fma2(acc[2][1], s2, w0.y);  fma2(acc[3][1], s3, w0.y);
                fma2(acc[0][2], s0, w1v.x); fma2(acc[1][2], s1, w1v.x); fma2(acc[2][2], s2, w1v.x); fma2(acc[3][2], s3, w1v.x);
                fma2(acc[0][3], s0, w1v.y); fma2(acc[1][3], s1, w1v.y); fma2(acc[2][3], s2, w1v.y); fma2(acc[3][3], s3, w1v.y);
                fma2(acc[0][4], s0, w2v.x); fma2(acc[1][4], s1, w2v.x); fma2(acc[2][4], s2, w2v.x); fma2(acc[3][4], s3, w2v.x);
                fma2(acc[0][5], s0, w2v.y); fma2(acc[1][5], s1, w2v.y); fma2(acc[2][5], s2, w2v.y); fma2(acc[3][5], s3, w2v.y);
            }
            __syncthreads();   // sp/sc reads done before H overwrites
            // store H: rows 0..31 -> spf, rows 32..47 -> scf
            #pragma unroll
            for (int op = 0; op < 6; op++) {
                int o = 12*ob + 2*op;          // o even; pair (o, o+1) never straddles 32
                float* r0 = (o < 32) ? (spf + o*NPX) : (scf + (o - 32)*NPX);
                float* r1 = r0 + NPX;
                #pragma unroll
                for (int m = 0; m < 4; m++) {
                    r0[g + 64*m] = fmaxf(lo2(acc[m][op]), 0.f);
                    r1[g + 64*m] = fmaxf(hi2(acc[m][op]), 0.f);
                }
            }
        }
        __syncthreads();

        // ---- GEMM2: cur = W2*H + residual; thread = (g2 in 128, jg of 8 j) ----
        {
            const int g2 = tid & 127;    // px = g2, g2+128
            const int jg = tid >> 7;     // j = 8*jg .. 8*jg+7
            const int pxA = g2, pxB = g2 + 128;
            const int pyA = pxA >> 4, sxA = pxA & 15;
            const int pyB = pxB >> 4, sxB = pxB & 15;

            // residual: masked cell re-read from global (sc is being reused for H)
            float rA[8], rB[8];
            {
                const int hwA = (gy0 + pyA)*Ww + gx0 + sxA;
                const int hwB = (gy0 + pyB)*Ww + gx0 + sxB;
                const unsigned char aA = arow[hwA];
                const unsigned char aB = arow[hwB];
                #pragma unroll
                for (int jj = 0; jj < 8; jj++) {
                    int j = 8*jg + jj;
                    const float* sj = src + (size_t)(n*CCH + j)*(Hh*Ww);
                    rA[jj] = aA ? sj[hwA] : 0.0f;
                    rB[jj] = aB ? sj[hwB] : 0.0f;
                }
            }

            ULL c0[4], c1[4];
            #pragma unroll
            for (int q = 0; q < 4; q++) { c0[q] = 0ull; c1[q] = 0ull; }

            #pragma unroll 8
            for (int o = 0; o < 32; o++) {
                const float* hs = spf + o*NPX;
                float ha = hs[g2], hb = hs[g2 + 128];
                ULL sa = pk2(ha,ha), sb = pk2(hb,hb);
                const ulonglong2* wv = (const ulonglong2*)(sw2f + o*16 + 8*jg);
                ulonglong2 w0 = wv[0], w1v = wv[1];
                fma2(c0[0], sa, w0.x); fma2(c0[1], sa, w0.y);
                fma2(c0[2], sa, w1v.x); fma2(c0[3], sa, w1v.y);
                fma2(c1[0], sb, w0.x); fma2(c1[1], sb, w0.y);
                fma2(c1[2], sb, w1v.x); fma2(c1[3], sb, w1v.y);
            }
            #pragma unroll 8
            for (int o = 32; o < 48; o++) {
                const float* hs = scf + (o - 32)*NPX;
                float ha = hs[g2], hb = hs[g2 + 128];
                ULL sa = pk2(ha,ha), sb = pk2(hb,hb);
                const ulonglong2* wv = (const ulonglong2*)(sw2f + o*16 + 8*jg);
                ulonglong2 w0 = wv[0], w1v = wv[1];
                fma2(c0[0], sa, w0.x); fma2(c0[1], sa, w0.y);
                fma2(c0[2], sa, w1v.x); fma2(c0[3], sa, w1v.y);
                fma2(c1[0], sb, w0.x); fma2(c1[1], sb, w0.y);
                fma2(c1[2], sb, w1v.x); fma2(c1[3], sb, w1v.y);
            }

            // store with residual
            const int hwA = (gy0 + pyA)*Ww + gx0 + sxA;
            const int hwB = (gy0 + pyB)*Ww + gx0 + sxB;
            #pragma unroll
            for (int q = 0; q < 4; q++) {
                int j = 8*jg + 2*q;
                float* d0 = dst + (size_t)(n*CCH + j)*(Hh*Ww);
                float* d1 = d0 + Hh*Ww;
                d0[hwA] = lo2(c0[q]) + rA[2*q];
                d1[hwA] = hi2(c0[q]) + rA[2*q + 1];
                d0[hwB] = lo2(c1[q]) + rB[2*q];
                d1[hwB] = hi2(c1[q]) + rB[2*q + 1];
            }
        }
        __syncthreads();   // H reads done before next tile's staging writes scf/spf
    }
}

// post mask (3x3 maxpool of new cur ch0) & alive byte; last iter writes output.
__global__ void alive_kernel(float* __restrict__ outfinal, int parity, int writeOut)
{
    const float* __restrict__ cur = parity ? g_bufA : g_bufB;
    int p = blockIdx.x*blockDim.x + threadIdx.x;
    if (p >= NB*Hh*Ww) return;
    int x = p % Ww;
    int y = (p / Ww) % Hh;
    int n = p / (Hh*Ww);
    const float* c0 = cur + (size_t)n*CCH*Hh*Ww;
    float m = -1e30f;
    #pragma unroll
    for (int dy = -1; dy <= 1; dy++) {
        int yy = y + dy;
        if (yy < 0 || yy >= Hh) continue;
        const float* row = c0 + yy*Ww;
        #pragma unroll
        for (int dx = -1; dx <= 1; dx++) {
            int xx = x + dx;
            if (xx < 0 || xx >= Ww) continue;
            m = fmaxf(m, row[xx]);
        }
    }
    bool alive = (m > 0.1f) && (g_pre[p] != 0);
    g_alive[p] = alive ? 1 : 0;
    if (writeOut) {
        size_t base = ((size_t)n*CCH)*Hh*Ww + (size_t)y*Ww + x;
        #pragma unroll
        for (int c = 1; c <= 10; c++) {
            float v = alive ? cur[base + (size_t)c*Hh*Ww] : 0.0f;
            outfinal[(((size_t)n*10 + (c-1))*Hh + y)*Ww + x] = v;
        }
    }
}

extern "C" void kernel_launch(void* const* d_in, const int* in_sizes, int n_in,
                              void* d_out, int out_size)
{
    const float *inp = nullptr, *w1 = nullptr, *w2 = nullptr;
    for (int i = 0; i < n_in; i++) {
        if (in_sizes[i] == 48*48)      w1 = (const float*)d_in[i];
        else if (in_sizes[i] == 16*48) w2 = (const float*)d_in[i];
        else                           inp = (const float*)d_in[i];
    }
    float* out = (float*)d_out;

    // 2304 + 768 + 8192 + 5184 floats = 16448 floats = 65792 B
    const int smemBytes = 16448*4;
    cudaFuncSetAttribute(step_kernel, cudaFuncAttributeMaxDynamicSharedMemorySize, smemBytes);

    init_kernel<<<(NB*CCH*Hh*Ww + 255)/256, 256>>>(inp);

    const int g2 = (NB*Hh*Ww + 255)/256;
    for (int it = 0; it < NITER; it++) {
        int parity = it & 1;
        step_kernel<<<NCTA, 256, smemBytes>>>(w1, w2, parity);
        alive_kernel<<<g2, 256>>>(out, parity, (it == NITER-1) ? 1 : 0);
    }
}